// round 7
// baseline (speedup 1.0000x reference)
#include <cuda_runtime.h>

// Problem constants (B=64, S=4096, D=256)
#define B_ 64
#define S_ 4096
#define D_ 256
#define NROWS (B_ * S_)          // 262144 = 2^18 flat rows
#define G_ 592                   // grid: 4 CTAs x 148 SMs (1 wave; ~3.9/SM on 152-SM GB300)
#define NWARPS 8
#define THREADS 256

// Balanced flat partition: block k owns rows [ceil(k*N/G), ceil((k+1)*N/G)).
// Row r belongs to block floor(r*G/N). All fit in 32-bit (N*G < 2^31).
__device__ __forceinline__ unsigned int row_lo(unsigned int k) {
    return (k * (unsigned int)NROWS + (G_ - 1)) / G_;
}

// Scratch: per-(block, segment) partials. A block spans <= 2 batches
// (443 rows < 4096), so <= 2 segments.
__device__ float g_acc[G_][2][D_];
__device__ float g_lsum[G_][2];
// Monotonic per-batch arrival counter; each call adds exactly exp(b) arrivals,
// so (count % exp(b)) == 0 detects the last contributor (graph-replay safe).
__device__ unsigned int g_cnt[B_];

// w = exp(tanh(x)) = e * exp(-2/(e^{2x}+1)); branch-free, robust at both tails.
__device__ __forceinline__ float exp_tanh(float x) {
    float t = __expf(2.0f * x);
    return 2.718281828f * __expf(__fdividef(-2.0f, t + 1.0f));
}

__global__ __launch_bounds__(THREADS, 4) void att_fused(
    const float* __restrict__ aspect,   // [B, 1, D]
    const float* __restrict__ memory,   // [B, S, D]
    const float* __restrict__ W,        // [2D, 1]
    const float* __restrict__ bias,     // [1]
    float* __restrict__ out)            // [B, D]
{
    const int blk  = blockIdx.x;
    const int tid  = threadIdx.x;
    const int warp = tid >> 5;
    const int lane = tid & 31;

    __shared__ float s_red[NWARPS];
    __shared__ float s_abias;
    __shared__ float s_acc[D_];
    __shared__ float s_l[NWARPS];
    __shared__ unsigned int s_last;

    const unsigned int r_lo = row_lo(blk);
    const unsigned int r_hi = row_lo(blk + 1);

    // Wm in registers: lane l holds W4[l] and W4[32+l] (R2 layout).
    const float4* W4 = (const float4*)W;
    const float4 wm0 = W4[lane];
    const float4 wm1 = W4[32 + lane];
    const float4* mem4 = (const float4*)memory;

    int seg = 0;
    for (unsigned int rs = r_hi > r_lo ? r_lo : r_hi; rs < r_hi; seg++) {
        const unsigned int b  = rs >> 12;                    // batch of this segment
        const unsigned int re = min(r_hi, (b + 1u) << 12);   // segment end

        // ---- aspect bias for batch b: dot(aspect[b], Wa) + bias ----
        {
            float p = aspect[b * D_ + tid] * W[D_ + tid];
            #pragma unroll
            for (int o = 16; o; o >>= 1) p += __shfl_xor_sync(0xffffffffu, p, o);
            if (lane == 0) s_red[warp] = p;
        }
        s_acc[tid] = 0.0f;
        __syncthreads();
        if (tid == 0) {
            float s = bias[0];
            #pragma unroll
            for (int w = 0; w < NWARPS; w++) s += s_red[w];
            s_abias = s;
        }
        __syncthreads();
        const float abias = s_abias;

        float4 a0 = make_float4(0.f, 0.f, 0.f, 0.f);
        float4 a1 = make_float4(0.f, 0.f, 0.f, 0.f);
        float lsum = 0.0f;

        // One RB=4 group: warp handles rows base + j*8 + warp, j=0..3.
        // 8 front-batched LDG.128 + 4 pipelined shuffle chains (R2's body).
        #define GROUP32(BASE)                                                          \
        {                                                                              \
            float4 v0[4], v1[4];                                                       \
            _Pragma("unroll")                                                          \
            for (int j = 0; j < 4; j++) {                                              \
                const float4* r = mem4 + (size_t)((BASE) + j * NWARPS + warp) * (D_/4);\
                v0[j] = r[lane];                                                       \
                v1[j] = r[32 + lane];                                                  \
            }                                                                          \
            float dot[4];                                                              \
            _Pragma("unroll")                                                          \
            for (int j = 0; j < 4; j++)                                                \
                dot[j] = v0[j].x*wm0.x + v0[j].y*wm0.y + v0[j].z*wm0.z + v0[j].w*wm0.w \
                       + v1[j].x*wm1.x + v1[j].y*wm1.y + v1[j].z*wm1.z + v1[j].w*wm1.w;\
            _Pragma("unroll")                                                          \
            for (int o = 16; o; o >>= 1) {                                             \
                _Pragma("unroll")                                                      \
                for (int j = 0; j < 4; j++)                                            \
                    dot[j] += __shfl_xor_sync(0xffffffffu, dot[j], o);                 \
            }                                                                          \
            _Pragma("unroll")                                                          \
            for (int j = 0; j < 4; j++) {                                              \
                const float w = exp_tanh(dot[j] + abias);                              \
                lsum += w;                                                             \
                a0.x += w*v0[j].x; a0.y += w*v0[j].y;                                  \
                a0.z += w*v0[j].z; a0.w += w*v0[j].w;                                  \
                a1.x += w*v1[j].x; a1.y += w*v1[j].y;                                  \
                a1.z += w*v1[j].z; a1.w += w*v1[j].w;                                  \
            }                                                                          \
        }

        unsigned int base = rs;
        // Main: 64 rows per iteration = two groups (mirrors R2's unroll-2 body).
        for (; base + 64 <= re; base += 64) {
            GROUP32(base)
            GROUP32(base + 32)
        }
        if (base + 32 <= re) { GROUP32(base) base += 32; }
        // Tail: per-row, warp-uniform predicate.
        #pragma unroll
        for (int j = 0; j < 4; j++) {
            const unsigned int row = base + j * NWARPS + warp;
            if (row < re) {
                const float4* r = mem4 + (size_t)row * (D_ / 4);
                const float4 v0 = r[lane];
                const float4 v1 = r[32 + lane];
                float dot = v0.x*wm0.x + v0.y*wm0.y + v0.z*wm0.z + v0.w*wm0.w
                          + v1.x*wm1.x + v1.y*wm1.y + v1.z*wm1.z + v1.w*wm1.w;
                #pragma unroll
                for (int o = 16; o; o >>= 1) dot += __shfl_xor_sync(0xffffffffu, dot, o);
                const float w = exp_tanh(dot + abias);
                lsum += w;
                a0.x += w*v0.x; a0.y += w*v0.y; a0.z += w*v0.z; a0.w += w*v0.w;
                a1.x += w*v1.x; a1.y += w*v1.y; a1.z += w*v1.z; a1.w += w*v1.w;
            }
        }
        #undef GROUP32

        // ---- combine 8 warps via smem atomics ----
        atomicAdd(&s_acc[lane * 4 + 0], a0.x);
        atomicAdd(&s_acc[lane * 4 + 1], a0.y);
        atomicAdd(&s_acc[lane * 4 + 2], a0.z);
        atomicAdd(&s_acc[lane * 4 + 3], a0.w);
        atomicAdd(&s_acc[128 + lane * 4 + 0], a1.x);
        atomicAdd(&s_acc[128 + lane * 4 + 1], a1.y);
        atomicAdd(&s_acc[128 + lane * 4 + 2], a1.z);
        atomicAdd(&s_acc[128 + lane * 4 + 3], a1.w);
        if (lane == 0) s_l[warp] = lsum;
        __syncthreads();

        // ---- publish this segment's partial ----
        g_acc[blk][seg][tid] = s_acc[tid];
        if (tid == 0) {
            float l = 0.f;
            #pragma unroll
            for (int w = 0; w < NWARPS; w++) l += s_l[w];
            g_lsum[blk][seg] = l;
        }

        // ---- last contributor for batch b combines ----
        __threadfence();
        const unsigned int blkL = (b * 4096u * G_) >> 18;            // first contributor
        const unsigned int blkH = ((b * 4096u + 4095u) * G_) >> 18;  // last contributor
        if (tid == 0) {
            const unsigned int expb = blkH - blkL + 1u;
            unsigned int old = atomicAdd(&g_cnt[b], 1u);
            s_last = (((old + 1u) % expb) == 0u) ? 1u : 0u;
        }
        __syncthreads();

        if (s_last) {
            float acc = 0.f, l = 0.f;
            for (unsigned int k = blkL; k <= blkH; k++) {
                const int sk = ((row_lo(k) >> 12) == b) ? 0 : 1;
                acc += g_acc[k][sk][tid];
                l   += g_lsum[k][sk];
            }
            out[b * D_ + tid] = acc / l;
        }
        __syncthreads();   // protect s_acc/s_last before next segment
        rs = re;
    }
}

extern "C" void kernel_launch(void* const* d_in, const int* in_sizes, int n_in,
                              void* d_out, int out_size)
{
    const float* aspect = (const float*)d_in[0];   // [B,1,D]
    const float* memory = (const float*)d_in[1];   // [B,S,D]
    const float* W      = (const float*)d_in[2];   // [2D,1]
    const float* bias   = (const float*)d_in[3];   // [1]
    float* out = (float*)d_out;                    // [B,D]

    att_fused<<<G_, THREADS>>>(aspect, memory, W, bias, out);
}